// round 5
// baseline (speedup 1.0000x reference)
#include <cuda_runtime.h>

#define NB 1024   // batch size, fixed by the problem

// ---------------------------------------------------------------------------
// Scratch: single __device__ global array (no allocations allowed).
// All intermediates live in [C, H, W, B] layout (batch innermost, f32).
// ---------------------------------------------------------------------------
__device__ float g_scratch[209938L * NB];

#define OFF_X0 0L
#define OFF_T0 635L
#define OFF_T1 3810L
#define OFF_X1 5835L
#define OFF_R0 15960L
#define OFF_Z1 16365L
#define OFF_T2 46740L
#define OFF_X2 62115L
#define OFF_R1 92865L
#define OFF_Z2 97990L
#define OFF_T3 147190L
#define OFF_ZF 168790L
#define OFF_R2 196438L

// packed fp32x2 FMA: d = a*b + d (element-wise on two packed floats)
#define FMA2(d, a, b) \
    asm("fma.rn.f32x2 %0, %1, %2, %0;" : "+l"(d) : "l"(a), "l"(b))

// ---------------------------------------------------------------------------
// Generic GEMM over [*, B] layout, templated on M-tile width OM.
// Double-buffered smem pipeline, register prefetch, ONE barrier/iteration.
// Inner product uses packed f32x2 FFMA2 along the b (batch) dimension:
//   - A tile float4 rows reinterpret directly as 2x f32x2 (no pack cost)
//   - W tile stored DUPLICATED (w,w) and interleaved [ (m%MR)*16 + m/MR ]
//     so reads are per-warp broadcasts (LDS.64, conflict-free)
//
// mode 0 (conv over H), mode 1 (semi-linear per group) as before.
// Tile: OM (m) x 128 (b); OM=128 -> BK=8 (smem cap), else BK=16. 256 threads.
// Thread computes MR m x 8 b as MR x 4 f32x2 accumulators.
// ---------------------------------------------------------------------------
template<int OM>
__global__ __launch_bounds__(256, OM >= 128 ? 1 : 2)
void gemm_k(const float* __restrict__ in, const float* __restrict__ Wt,
            const float* __restrict__ bias, const float* __restrict__ addsrc,
            float* __restrict__ out,
            int K, int O, int KH, int pad, int Hin, int Wd, int Hout,
            int mode, int relu)
{
    constexpr int BK  = (OM >= 128) ? 8 : 16;
    constexpr int MR  = OM / 16;           // m per thread: 8 / 4 / 2
    constexpr int AT  = BK / 8;            // A-load float4 iterations
    constexpr int WT  = OM * BK / 256;     // W-load iterations
    constexpr int KSH = (BK == 8) ? 3 : 4; // log2(BK)

    __shared__ float  As[2][BK][128];      // [buf][k][b], 512B rows
    __shared__ float2 Ws[2][BK][OM + 1];   // duplicated (w,w); +1 pad de-conflicts stores

    const int tid = threadIdx.x;
    const int n0  = blockIdx.x * 128;   // batch tile start
    const int m0  = blockIdx.y * OM;    // output-feature tile start
    const int pos = blockIdx.z;         // conv: h*Wd+w ; lin: group index
    int h = pos, w = 0;
    if (mode == 0) { h = pos / Wd; w = pos - h * Wd; }

    const int tn = tid & 15;   // b sub-tile: 4 at tn*4, 4 at 64+tn*4
    const int tm = tid >> 4;   // m sub-tile: MR rows, m = m0 + tm*MR + i

    unsigned long long acc2[MR][4];    // f32x2 accumulators; 0ull == (0.f,0.f)
    #pragma unroll
    for (int i = 0; i < MR; i++)
        #pragma unroll
        for (int j = 0; j < 4; j++) acc2[i][j] = 0ull;

    // ---- tile loaders (gmem -> regs) and committer (regs -> smem) ----
    float4 va[AT];
    float  wv[WT];

    auto loadTiles = [&](int k0) {
        #pragma unroll
        for (int t = 0; t < AT; t++) {
            int idx = tid + t * 256;
            int kk  = idx >> 5;             // 0..BK-1
            int c4  = (idx & 31) << 2;      // 0,4,...,124
            int k   = k0 + kk;
            float4 v = make_float4(0.f, 0.f, 0.f, 0.f);
            if (k < K) {
                int off = -1;
                if (mode == 0) {
                    int ci, kh;
                    if (KH == 1) { ci = k; kh = 0; }
                    else         { ci = k / KH; kh = k - ci * KH; }
                    int hi = h + kh - pad;
                    if (hi >= 0 && hi < Hin)
                        off = ((ci * Hin + hi) * Wd + w) * NB;
                } else {
                    off = (pos * K + k) * NB;
                }
                if (off >= 0)
                    v = *(const float4*)(in + off + n0 + c4);
            }
            va[t] = v;
        }
        #pragma unroll
        for (int t = 0; t < WT; t++) {
            int idx = tid + t * 256;
            int kk  = idx & (BK - 1);
            int mm  = idx >> KSH;           // 0..OM-1
            int m   = m0 + mm;
            int k   = k0 + kk;
            wv[t] = (m < O && k < K) ? Wt[m * K + k] : 0.f;
        }
    };

    auto storeTiles = [&](int buf) {
        #pragma unroll
        for (int t = 0; t < AT; t++) {
            int idx = tid + t * 256;
            int kk  = idx >> 5;
            int c4  = (idx & 31) << 2;
            *(float4*)(&As[buf][kk][c4]) = va[t];
        }
        #pragma unroll
        for (int t = 0; t < WT; t++) {
            int idx = tid + t * 256;
            int kk  = idx & (BK - 1);
            int mm  = idx >> KSH;
            // interleave: m = tm*MR + i stored at slot i*16 + tm
            int loc = (mm & (MR - 1)) * 16 + (mm / MR);
            Ws[buf][kk][loc] = make_float2(wv[t], wv[t]);
        }
    };

    const int nk = (K + BK - 1) / BK;
    loadTiles(0);
    storeTiles(0);
    __syncthreads();

    int buf = 0;
    for (int it = 0; it < nk; it++) {
        // prefetch next tile into regs (gmem latency overlaps compute below)
        if (it + 1 < nk) loadTiles((it + 1) * BK);

        // ---- OM x 128 rank-BK update: MR*4 FFMA2 per k per thread ----
        #pragma unroll
        for (int kk = 0; kk < BK; kk++) {
            const unsigned long long* wrow =
                reinterpret_cast<const unsigned long long*>(&Ws[buf][kk][0]);
            unsigned long long w2[MR];
            #pragma unroll
            for (int i = 0; i < MR; i++)
                w2[i] = wrow[i * 16 + tm];           // (w,w) broadcast, LDS.64

            ulonglong2 a01 = *reinterpret_cast<const ulonglong2*>(&As[buf][kk][tn * 4]);
            ulonglong2 a23 = *reinterpret_cast<const ulonglong2*>(&As[buf][kk][64 + tn * 4]);
            unsigned long long ar[4] = {a01.x, a01.y, a23.x, a23.y};

            #pragma unroll
            for (int i = 0; i < MR; i++)
                #pragma unroll
                for (int j = 0; j < 4; j++)
                    FMA2(acc2[i][j], w2[i], ar[j]);
        }

        // commit next tile to the other buffer; single barrier per iteration
        if (it + 1 < nk) storeTiles(buf ^ 1);
        __syncthreads();
        buf ^= 1;
    }

    // ---- epilogue: bias + optional residual + optional relu, float4 stores ----
    #pragma unroll
    for (int i = 0; i < MR; i++) {
        int m = m0 + tm * MR + i;
        if (m >= O) continue;
        int obase;
        if (mode == 0) obase = ((m * Hout + h) * Wd + w) * NB;
        else           obase = (pos * O + m) * NB;
        float bv = bias[m];
        #pragma unroll
        for (int half = 0; half < 2; half++) {
            int o = obase + n0 + half * 64 + tn * 4;
            float2 lo = *reinterpret_cast<float2*>(&acc2[i][half * 2 + 0]);
            float2 hi = *reinterpret_cast<float2*>(&acc2[i][half * 2 + 1]);
            float4 r;
            r.x = lo.x + bv; r.y = lo.y + bv;
            r.z = hi.x + bv; r.w = hi.y + bv;
            if (addsrc) {
                float4 a = *(const float4*)(addsrc + o);
                r.x += a.x; r.y += a.y; r.z += a.z; r.w += a.w;
            }
            if (relu) {
                r.x = fmaxf(r.x, 0.f); r.y = fmaxf(r.y, 0.f);
                r.z = fmaxf(r.z, 0.f); r.w = fmaxf(r.w, 0.f);
            }
            *(float4*)(out + o) = r;
        }
    }
}

// ---------------------------------------------------------------------------
// Transposes between harness [B, F] layout and internal [F, B] layout.
// ---------------------------------------------------------------------------
__global__ void transpose_bf_to_fb(const float* __restrict__ src,
                                   float* __restrict__ dst, int F)
{
    __shared__ float tile[32][33];
    int f0 = blockIdx.x * 32, b0 = blockIdx.y * 32;
    #pragma unroll
    for (int r = threadIdx.y; r < 32; r += 8) {
        int b = b0 + r, f = f0 + threadIdx.x;
        tile[r][threadIdx.x] = (f < F) ? src[b * F + f] : 0.f;  // coalesced over f
    }
    __syncthreads();
    #pragma unroll
    for (int r = threadIdx.y; r < 32; r += 8) {
        int f = f0 + r, b = b0 + threadIdx.x;
        if (f < F) dst[f * NB + b] = tile[threadIdx.x][r];      // coalesced over b
    }
}

__global__ void transpose_fb_to_bf(const float* __restrict__ src,
                                   float* __restrict__ dst, int F)
{
    __shared__ float tile[32][33];
    int f0 = blockIdx.x * 32, b0 = blockIdx.y * 32;
    #pragma unroll
    for (int r = threadIdx.y; r < 32; r += 8) {
        int f = f0 + r;
        tile[r][threadIdx.x] = (f < F) ? src[f * NB + b0 + threadIdx.x] : 0.f;
    }
    __syncthreads();
    #pragma unroll
    for (int r = threadIdx.y; r < 32; r += 8) {
        int f = f0 + threadIdx.x, b = b0 + r;
        if (f < F) dst[b * F + f] = tile[threadIdx.x][r];       // coalesced over f
    }
}

// ---------------------------------------------------------------------------
// Host-side helpers: pick the M-tile minimizing padded m-slots.
// ---------------------------------------------------------------------------
static inline void launch_gemm(const float* in, const float* Wt, const float* bias,
                               const float* addsrc, float* out,
                               int K, int O, int KH, int pad, int Hin, int Wd,
                               int Hout, int mode, int relu, int zdim)
{
    if (O % 128 == 0) {
        dim3 grid(NB / 128, O / 128, zdim);
        gemm_k<128><<<grid, 256>>>(in, Wt, bias, addsrc, out,
                                   K, O, KH, pad, Hin, Wd, Hout, mode, relu);
        return;
    }
    int s32 = ((O + 31) / 32) * 32;
    int s64 = ((O + 63) / 64) * 64;
    if (s32 < s64) {
        dim3 grid(NB / 128, (O + 31) / 32, zdim);
        gemm_k<32><<<grid, 256>>>(in, Wt, bias, addsrc, out,
                                  K, O, KH, pad, Hin, Wd, Hout, mode, relu);
    } else {
        dim3 grid(NB / 128, (O + 63) / 64, zdim);
        gemm_k<64><<<grid, 256>>>(in, Wt, bias, addsrc, out,
                                  K, O, KH, pad, Hin, Wd, Hout, mode, relu);
    }
}

static inline void conv_h(const float* in, const float* Wt, const float* bias,
                          const float* addsrc, float* out,
                          int Ci, int KH, int pad, int Hin, int Wd, int O, int Hout)
{
    launch_gemm(in, Wt, bias, addsrc, out,
                Ci * KH, O, KH, pad, Hin, Wd, Hout, /*mode=*/0, /*relu=*/0,
                Hout * Wd);
}

static inline void semi_lin(const float* in, const float* Wt, const float* bias,
                            float* out, int G, int Win, int Wout, int relu)
{
    launch_gemm(in, Wt, bias, nullptr, out,
                Win, Wout, 1, 0, 0, 0, 0, /*mode=*/1, relu, G);
}

extern "C" void kernel_launch(void* const* d_in, const int* in_sizes, int n_in,
                              void* d_out, int out_size)
{
    const float* x   = (const float*)d_in[0];
    const float* W0a = (const float*)d_in[1];  const float* b0a = (const float*)d_in[2];
    const float* Wl0 = (const float*)d_in[3];  const float* bl0 = (const float*)d_in[4];
    const float* W0b = (const float*)d_in[5];  const float* b0b = (const float*)d_in[6];
    const float* Wr0 = (const float*)d_in[7];  const float* br0 = (const float*)d_in[8];
    const float* W0c = (const float*)d_in[9];  const float* b0c = (const float*)d_in[10];
    const float* W1  = (const float*)d_in[11]; const float* b1  = (const float*)d_in[12];
    const float* Wl1 = (const float*)d_in[13]; const float* bl1 = (const float*)d_in[14];
    const float* W2  = (const float*)d_in[15]; const float* b2  = (const float*)d_in[16];
    const float* Wra = (const float*)d_in[17]; const float* bra = (const float*)d_in[18];
    const float* Wa  = (const float*)d_in[19]; const float* ba  = (const float*)d_in[20];
    const float* W3  = (const float*)d_in[21]; const float* b3  = (const float*)d_in[22];
    const float* Wl2 = (const float*)d_in[23]; const float* bl2 = (const float*)d_in[24];
    const float* W4  = (const float*)d_in[25]; const float* b4  = (const float*)d_in[26];
    const float* Wrb = (const float*)d_in[27]; const float* brb = (const float*)d_in[28];
    const float* Wb  = (const float*)d_in[29]; const float* bb  = (const float*)d_in[30];

    float* S = nullptr;
    cudaGetSymbolAddress((void**)&S, g_scratch);
    float* X0 = S + OFF_X0 * NB;
    float* t0 = S + OFF_T0 * NB;
    float* t1 = S + OFF_T1 * NB;
    float* x1 = S + OFF_X1 * NB;
    float* r0 = S + OFF_R0 * NB;
    float* z1 = S + OFF_Z1 * NB;
    float* t2 = S + OFF_T2 * NB;
    float* x2 = S + OFF_X2 * NB;
    float* r1 = S + OFF_R1 * NB;
    float* z2 = S + OFF_Z2 * NB;
    float* t3 = S + OFF_T3 * NB;
    float* zf = S + OFF_ZF * NB;
    float* r2 = S + OFF_R2 * NB;

    // x [B,1,5,127] -> X0 [1,5,127,B]
    {
        dim3 g((635 + 31) / 32, NB / 32), b(32, 8);
        transpose_bf_to_fb<<<g, b>>>(x, X0, 635);
    }

    // ---- block 0 ----
    conv_h(X0, W0a, b0a, nullptr, t0, /*Ci*/1, /*KH*/3, /*pad*/1, /*Hin*/5, /*Wd*/127, /*O*/5,  /*Hout*/5);
    semi_lin(t0, Wl0, bl0, t1, /*G*/25, /*Win*/127, /*Wout*/81, /*relu*/1);
    conv_h(t1, W0b, b0b, nullptr, x1, 5, 3, 1, 5, 81, 25, 5);
    semi_lin(X0, Wr0, br0, r0, 5, 127, 81, 0);
    conv_h(r0, W0c, b0c, x1, x1, 1, 1, 0, 5, 81, 25, 5);       // x1 += 1x1 conv

    // ---- block 1 ----
    conv_h(x1, W1, b1, nullptr, z1, 25, 3, 1, 5, 81, 75, 5);
    semi_lin(z1, Wl1, bl1, t2, 375, 81, 41, 1);
    conv_h(t2, W2, b2, nullptr, x2, 75, 3, 1, 5, 41, 150, 5);
    semi_lin(x1, Wra, bra, r1, 125, 81, 41, 0);
    conv_h(r1, Wa, ba, x2, x2, 25, 1, 0, 5, 41, 150, 5);       // x2 += 1x1 conv

    // ---- block 2 ----
    conv_h(x2, W3, b3, nullptr, z2, 150, 2, 0, 5, 41, 300, 4);
    semi_lin(z2, Wl2, bl2, t3, 1200, 41, 18, 1);
    conv_h(t3, W4, b4, nullptr, zf, 300, 2, 0, 4, 18, 512, 3);
    semi_lin(x2, Wrb, brb, r2, 750, 41, 18, 0);
    conv_h(r2, Wb, bb, zf, zf, 150, 3, 0, 5, 18, 512, 3);      // zf += residual conv

    // zf [512,3,18,B] -> d_out [B,512,3,18]
    {
        dim3 g(27648 / 32, NB / 32), b(32, 8);
        transpose_fb_to_bf<<<g, b>>>(zf, (float*)d_out, 27648);
    }
}

// round 9
// speedup vs baseline: 1.1408x; 1.1408x over previous
#include <cuda_runtime.h>

#define NB 1024   // batch size, fixed by the problem

// ---------------------------------------------------------------------------
// Scratch: single __device__ global array (no allocations allowed).
// All intermediates live in [C, H, W, B] layout (batch innermost, f32).
// ---------------------------------------------------------------------------
__device__ float g_scratch[209938L * NB];

#define OFF_X0 0L
#define OFF_T0 635L
#define OFF_T1 3810L
#define OFF_X1 5835L
#define OFF_R0 15960L
#define OFF_Z1 16365L
#define OFF_T2 46740L
#define OFF_X2 62115L
#define OFF_R1 92865L
#define OFF_Z2 97990L
#define OFF_T3 147190L
#define OFF_ZF 168790L
#define OFF_R2 196438L

// ---------------------------------------------------------------------------
// Generic GEMM kernel over [*, B] layout, templated on M-tile width OM.
// Double-buffered smem pipeline: next tile prefetched into registers during
// compute, stored to the alternate buffer, ONE __syncthreads per iteration.
//
// mode 0 (conv over H): out[((m*Hout + h)*Wd + w)*NB + b] =
//     sum_{k=(ci,kh)} W[m*K + k] * in[((ci*Hin + h+kh-pad)*Wd + w)*NB + b]
// mode 1 (semi-linear per group): out[(pos*O + m)*NB + b] =
//     sum_k W[m*K + k] * in[(pos*K + k)*NB + b]
//
// Tile: OM (m) x 128 (b), 256 threads. OM=128 -> BK=8 (smem), else BK=16.
// OM=128: 8m x 8b/thread, 1 CTA/SM. OM=64: 4m x 8b, 2 CTA/SM.
// OM=32:  2m x 8b, 4 CTA/SM (reg-capped to 64 -> double occupancy for the
//         latency-bound small-K ops, which profile at issue<48%).
// Epilogue fuses bias, optional residual add (addsrc), optional ReLU.
// ---------------------------------------------------------------------------
template<int OM>
__global__ __launch_bounds__(256, OM >= 128 ? 1 : (OM == 32 ? 4 : 2))
void gemm_k(const float* __restrict__ in, const float* __restrict__ Wt,
            const float* __restrict__ bias, const float* __restrict__ addsrc,
            float* __restrict__ out,
            int K, int O, int KH, int pad, int Hin, int Wd, int Hout,
            int mode, int relu)
{
    constexpr int BK  = (OM >= 128) ? 8 : 16;
    constexpr int MR  = OM / 16;           // m per thread: 8 / 4 / 2
    constexpr int AT  = BK / 8;            // A-load float4 iterations
    constexpr int WT  = OM * BK / 256;     // W-load iterations
    __shared__ float As[2][BK][128];       // [buf][k][b], 512B rows
    __shared__ float Ws[2][BK][OM + 4];    // [buf][k][m], +4 pad (16B-aligned rows)

    const int tid = threadIdx.x;
    const int n0  = blockIdx.x * 128;   // batch tile start
    const int m0  = blockIdx.y * OM;    // output-feature tile start
    const int pos = blockIdx.z;         // conv: h*Wd+w ; lin: group index
    int h = pos, w = 0;
    if (mode == 0) { h = pos / Wd; w = pos - h * Wd; }

    const int tn = tid & 15;   // b sub-tile: 4 at tn*4, 4 at 64+tn*4
    const int tm = tid >> 4;   // m sub-tile: MR rows at tm*MR

    float acc[MR][8];
    #pragma unroll
    for (int i = 0; i < MR; i++)
        #pragma unroll
        for (int j = 0; j < 8; j++) acc[i][j] = 0.f;

    // ---- tile loaders (gmem -> regs) and committer (regs -> smem) ----
    float4 va[AT];
    float  wv[WT];

    auto loadTiles = [&](int k0) {
        #pragma unroll
        for (int t = 0; t < AT; t++) {
            int idx = tid + t * 256;
            int kk  = idx >> 5;             // 0..BK-1
            int c4  = (idx & 31) << 2;      // 0,4,...,124
            int k   = k0 + kk;
            float4 v = make_float4(0.f, 0.f, 0.f, 0.f);
            if (k < K) {
                int off = -1;
                if (mode == 0) {
                    int ci, kh;
                    if (KH == 1) { ci = k; kh = 0; }
                    else         { ci = k / KH; kh = k - ci * KH; }
                    int hi = h + kh - pad;
                    if (hi >= 0 && hi < Hin)
                        off = ((ci * Hin + hi) * Wd + w) * NB;
                } else {
                    off = (pos * K + k) * NB;
                }
                if (off >= 0)
                    v = *(const float4*)(in + off + n0 + c4);
            }
            va[t] = v;
        }
        #pragma unroll
        for (int t = 0; t < WT; t++) {     // OM*BK entries / 256 threads
            int idx = tid + t * 256;
            int mm  = idx / BK;            // 0..OM-1
            int kk  = idx % BK;
            int m   = m0 + mm;
            int k   = k0 + kk;
            wv[t] = (m < O && k < K) ? Wt[m * K + k] : 0.f;
        }
    };

    auto storeTiles = [&](int buf) {
        #pragma unroll
        for (int t = 0; t < AT; t++) {
            int idx = tid + t * 256;
            int kk  = idx >> 5;
            int c4  = (idx & 31) << 2;
            *(float4*)(&As[buf][kk][c4]) = va[t];
        }
        #pragma unroll
        for (int t = 0; t < WT; t++) {
            int idx = tid + t * 256;
            int mm  = idx / BK;
            int kk  = idx % BK;
            Ws[buf][kk][mm] = wv[t];
        }
    };

    const int nk = (K + BK - 1) / BK;
    loadTiles(0);
    storeTiles(0);
    __syncthreads();

    int buf = 0;
    for (int it = 0; it < nk; it++) {
        // prefetch next tile into regs (gmem latency overlaps compute below)
        if (it + 1 < nk) loadTiles((it + 1) * BK);

        // ---- OM x 128 rank-BK update: MR*8 FFMA per k per thread ----
        #pragma unroll
        for (int kk = 0; kk < BK; kk++) {
            float wr[MR];
            if constexpr (MR == 8) {
                float4 v0 = *(const float4*)(&Ws[buf][kk][tm * 8]);
                float4 v1 = *(const float4*)(&Ws[buf][kk][tm * 8 + 4]);
                wr[0] = v0.x; wr[1] = v0.y; wr[2] = v0.z; wr[3] = v0.w;
                wr[4] = v1.x; wr[5] = v1.y; wr[6] = v1.z; wr[7] = v1.w;
            } else if constexpr (MR == 4) {
                float4 v = *(const float4*)(&Ws[buf][kk][tm * 4]);
                wr[0] = v.x; wr[1] = v.y; wr[2] = v.z; wr[3] = v.w;
            } else {
                float2 v = *(const float2*)(&Ws[buf][kk][tm * 2]);
                wr[0] = v.x; wr[1] = v.y;
            }
            float4 a0  = *(const float4*)(&As[buf][kk][tn * 4]);
            float4 a1  = *(const float4*)(&As[buf][kk][64 + tn * 4]);
            float ar[8] = {a0.x, a0.y, a0.z, a0.w, a1.x, a1.y, a1.z, a1.w};
            #pragma unroll
            for (int i = 0; i < MR; i++)
                #pragma unroll
                for (int j = 0; j < 8; j++)
                    acc[i][j] += wr[i] * ar[j];
        }

        // commit next tile to the other buffer; single barrier per iteration
        if (it + 1 < nk) storeTiles(buf ^ 1);
        __syncthreads();
        buf ^= 1;
    }

    // ---- epilogue: bias + optional residual + optional relu, float4 stores ----
    #pragma unroll
    for (int i = 0; i < MR; i++) {
        int m = m0 + tm * MR + i;
        if (m >= O) continue;
        int obase;
        if (mode == 0) obase = ((m * Hout + h) * Wd + w) * NB;
        else           obase = (pos * O + m) * NB;
        float bv = bias[m];
        #pragma unroll
        for (int half = 0; half < 2; half++) {
            int o = obase + n0 + half * 64 + tn * 4;
            float4 r;
            r.x = acc[i][half * 4 + 0] + bv;
            r.y = acc[i][half * 4 + 1] + bv;
            r.z = acc[i][half * 4 + 2] + bv;
            r.w = acc[i][half * 4 + 3] + bv;
            if (addsrc) {
                float4 a = *(const float4*)(addsrc + o);
                r.x += a.x; r.y += a.y; r.z += a.z; r.w += a.w;
            }
            if (relu) {
                r.x = fmaxf(r.x, 0.f); r.y = fmaxf(r.y, 0.f);
                r.z = fmaxf(r.z, 0.f); r.w = fmaxf(r.w, 0.f);
            }
            *(float4*)(out + o) = r;
        }
    }
}

// ---------------------------------------------------------------------------
// Transposes between harness [B, F] layout and internal [F, B] layout.
// ---------------------------------------------------------------------------
__global__ void transpose_bf_to_fb(const float* __restrict__ src,
                                   float* __restrict__ dst, int F)
{
    __shared__ float tile[32][33];
    int f0 = blockIdx.x * 32, b0 = blockIdx.y * 32;
    #pragma unroll
    for (int r = threadIdx.y; r < 32; r += 8) {
        int b = b0 + r, f = f0 + threadIdx.x;
        tile[r][threadIdx.x] = (f < F) ? src[b * F + f] : 0.f;  // coalesced over f
    }
    __syncthreads();
    #pragma unroll
    for (int r = threadIdx.y; r < 32; r += 8) {
        int f = f0 + r, b = b0 + threadIdx.x;
        if (f < F) dst[f * NB + b] = tile[threadIdx.x][r];      // coalesced over b
    }
}

__global__ void transpose_fb_to_bf(const float* __restrict__ src,
                                   float* __restrict__ dst, int F)
{
    __shared__ float tile[32][33];
    int f0 = blockIdx.x * 32, b0 = blockIdx.y * 32;
    #pragma unroll
    for (int r = threadIdx.y; r < 32; r += 8) {
        int f = f0 + r;
        tile[r][threadIdx.x] = (f < F) ? src[f * NB + b0 + threadIdx.x] : 0.f;
    }
    __syncthreads();
    #pragma unroll
    for (int r = threadIdx.y; r < 32; r += 8) {
        int f = f0 + threadIdx.x, b = b0 + r;
        if (f < F) dst[b * F + f] = tile[threadIdx.x][r];       // coalesced over f
    }
}

// ---------------------------------------------------------------------------
// Host-side helpers: pick the M-tile minimizing padded m-slots.
// OM=128 only when O is an exact multiple (O=512 ops), else 64/32.
// ---------------------------------------------------------------------------
static inline void launch_gemm(const float* in, const float* Wt, const float* bias,
                               const float* addsrc, float* out,
                               int K, int O, int KH, int pad, int Hin, int Wd,
                               int Hout, int mode, int relu, int zdim)
{
    if (O % 128 == 0) {
        dim3 grid(NB / 128, O / 128, zdim);
        gemm_k<128><<<grid, 256>>>(in, Wt, bias, addsrc, out,
                                   K, O, KH, pad, Hin, Wd, Hout, mode, relu);
        return;
    }
    int s32 = ((O + 31) / 32) * 32;
    int s64 = ((O + 63) / 64) * 64;
    if (s32 < s64) {
        dim3 grid(NB / 128, (O + 31) / 32, zdim);
        gemm_k<32><<<grid, 256>>>(in, Wt, bias, addsrc, out,
                                  K, O, KH, pad, Hin, Wd, Hout, mode, relu);
    } else {
        dim3 grid(NB / 128, (O + 63) / 64, zdim);
        gemm_k<64><<<grid, 256>>>(in, Wt, bias, addsrc, out,
                                  K, O, KH, pad, Hin, Wd, Hout, mode, relu);
    }
}

static inline void conv_h(const float* in, const float* Wt, const float* bias,
                          const float* addsrc, float* out,
                          int Ci, int KH, int pad, int Hin, int Wd, int O, int Hout)
{
    launch_gemm(in, Wt, bias, addsrc, out,
                Ci * KH, O, KH, pad, Hin, Wd, Hout, /*mode=*/0, /*relu=*/0,
                Hout * Wd);
}

static inline void semi_lin(const float* in, const float* Wt, const float* bias,
                            float* out, int G, int Win, int Wout, int relu)
{
    launch_gemm(in, Wt, bias, nullptr, out,
                Win, Wout, 1, 0, 0, 0, 0, /*mode=*/1, relu, G);
}

extern "C" void kernel_launch(void* const* d_in, const int* in_sizes, int n_in,
                              void* d_out, int out_size)
{
    const float* x   = (const float*)d_in[0];
    const float* W0a = (const float*)d_in[1];  const float* b0a = (const float*)d_in[2];
    const float* Wl0 = (const float*)d_in[3];  const float* bl0 = (const float*)d_in[4];
    const float* W0b = (const float*)d_in[5];  const float* b0b = (const float*)d_in[6];
    const float* Wr0 = (const float*)d_in[7];  const float* br0 = (const float*)d_in[8];
    const float* W0c = (const float*)d_in[9];  const float* b0c = (const float*)d_in[10];
    const float* W1  = (const float*)d_in[11]; const float* b1  = (const float*)d_in[12];
    const float* Wl1 = (const float*)d_in[13]; const float* bl1 = (const float*)d_in[14];
    const float* W2  = (const float*)d_in[15]; const float* b2  = (const float*)d_in[16];
    const float* Wra = (const float*)d_in[17]; const float* bra = (const float*)d_in[18];
    const float* Wa  = (const float*)d_in[19]; const float* ba  = (const float*)d_in[20];
    const float* W3  = (const float*)d_in[21]; const float* b3  = (const float*)d_in[22];
    const float* Wl2 = (const float*)d_in[23]; const float* bl2 = (const float*)d_in[24];
    const float* W4  = (const float*)d_in[25]; const float* b4  = (const float*)d_in[26];
    const float* Wrb = (const float*)d_in[27]; const float* brb = (const float*)d_in[28];
    const float* Wb  = (const float*)d_in[29]; const float* bb  = (const float*)d_in[30];

    float* S = nullptr;
    cudaGetSymbolAddress((void**)&S, g_scratch);
    float* X0 = S + OFF_X0 * NB;
    float* t0 = S + OFF_T0 * NB;
    float* t1 = S + OFF_T1 * NB;
    float* x1 = S + OFF_X1 * NB;
    float* r0 = S + OFF_R0 * NB;
    float* z1 = S + OFF_Z1 * NB;
    float* t2 = S + OFF_T2 * NB;
    float* x2 = S + OFF_X2 * NB;
    float* r1 = S + OFF_R1 * NB;
    float* z2 = S + OFF_Z2 * NB;
    float* t3 = S + OFF_T3 * NB;
    float* zf = S + OFF_ZF * NB;
    float* r2 = S + OFF_R2 * NB;

    // x [B,1,5,127] -> X0 [1,5,127,B]
    {
        dim3 g((635 + 31) / 32, NB / 32), b(32, 8);
        transpose_bf_to_fb<<<g, b>>>(x, X0, 635);
    }

    // ---- block 0 ----
    conv_h(X0, W0a, b0a, nullptr, t0, /*Ci*/1, /*KH*/3, /*pad*/1, /*Hin*/5, /*Wd*/127, /*O*/5,  /*Hout*/5);
    semi_lin(t0, Wl0, bl0, t1, /*G*/25, /*Win*/127, /*Wout*/81, /*relu*/1);
    conv_h(t1, W0b, b0b, nullptr, x1, 5, 3, 1, 5, 81, 25, 5);
    semi_lin(X0, Wr0, br0, r0, 5, 127, 81, 0);
    conv_h(r0, W0c, b0c, x1, x1, 1, 1, 0, 5, 81, 25, 5);       // x1 += 1x1 conv

    // ---- block 1 ----
    conv_h(x1, W1, b1, nullptr, z1, 25, 3, 1, 5, 81, 75, 5);
    semi_lin(z1, Wl1, bl1, t2, 375, 81, 41, 1);
    conv_h(t2, W2, b2, nullptr, x2, 75, 3, 1, 5, 41, 150, 5);
    semi_lin(x1, Wra, bra, r1, 125, 81, 41, 0);
    conv_h(r1, Wa, ba, x2, x2, 25, 1, 0, 5, 41, 150, 5);       // x2 += 1x1 conv

    // ---- block 2 ----
    conv_h(x2, W3, b3, nullptr, z2, 150, 2, 0, 5, 41, 300, 4);
    semi_lin(z2, Wl2, bl2, t3, 1200, 41, 18, 1);
    conv_h(t3, W4, b4, nullptr, zf, 300, 2, 0, 4, 18, 512, 3);
    semi_lin(x2, Wrb, brb, r2, 750, 41, 18, 0);
    conv_h(r2, Wb, bb, zf, zf, 150, 3, 0, 5, 18, 512, 3);      // zf += residual conv

    // zf [512,3,18,B] -> d_out [B,512,3,18]
    {
        dim3 g(27648 / 32, NB / 32), b(32, 8);
        transpose_fb_to_bf<<<g, b>>>(zf, (float*)d_out, 27648);
    }
}